// round 12
// baseline (speedup 1.0000x reference)
#include <cuda_runtime.h>
#include <cuda_fp16.h>
#include <cstdint>

// Problem constants
#define Bdim 8
#define Nseq 2048
#define Edim 1024
#define Hh   16
#define Dd   64
#define Mrows (Bdim * Nseq)      // 16384

// ---------------------------------------------------------------------------
// Scratch (allocation-free rule: __device__ globals)
// ---------------------------------------------------------------------------
__device__ float   g_qkv[(size_t)Mrows * 3 * Edim];   // 192 MB fp32
__device__ __half  g_xh [(size_t)Mrows * Edim];       // x as fp16
__device__ __half  g_ath[(size_t)Mrows * Edim];       // attn out as fp16
__device__ __half  g_wqh[(size_t)3 * Edim * Edim];    // Wqkv fp16
__device__ __half  g_woh[(size_t)Edim * Edim];        // Wo fp16

// ---------------------------------------------------------------------------
// Helpers (baseline-feature PTX only: cp.async, ldmatrix, mma.sync — sm_80+)
// ---------------------------------------------------------------------------
__device__ __forceinline__ uint32_t smem_u32(const void* p) {
    uint32_t a;
    asm("{ .reg .u64 t; cvta.to.shared.u64 t, %1; cvt.u32.u64 %0, t; }" : "=r"(a) : "l"(p));
    return a;
}
#define SWZ(x) ((x) ^ (((x) >> 3) & 0x70))

__device__ __forceinline__ void cp16(uint32_t dst, const void* src) {
    asm volatile("cp.async.cg.shared.global [%0], [%1], 16;" :: "r"(dst), "l"(src));
}
__device__ __forceinline__ void ldm4(uint32_t* r, uint32_t addr) {
    asm volatile("ldmatrix.sync.aligned.m8n8.x4.shared.b16 {%0,%1,%2,%3}, [%4];"
                 : "=r"(r[0]), "=r"(r[1]), "=r"(r[2]), "=r"(r[3]) : "r"(addr));
}
__device__ __forceinline__ void mma_f16(float* c, const uint32_t* a, uint32_t b0, uint32_t b1) {
    asm volatile(
        "mma.sync.aligned.m16n8k16.row.col.f32.f16.f16.f32 "
        "{%0,%1,%2,%3}, {%4,%5,%6,%7}, {%8,%9}, {%0,%1,%2,%3};"
        : "+f"(c[0]), "+f"(c[1]), "+f"(c[2]), "+f"(c[3])
        : "r"(a[0]), "r"(a[1]), "r"(a[2]), "r"(a[3]), "r"(b0), "r"(b1));
}

// ---------------------------------------------------------------------------
// fp32 -> fp16 conversion kernel
// ---------------------------------------------------------------------------
__global__ __launch_bounds__(256)
void tohalf_kernel(const float4* __restrict__ src, uint2* __restrict__ dst, int n4)
{
    int i = blockIdx.x * 256 + threadIdx.x;
    if (i >= n4) return;
    float4 v = src[i];
    __half2 p0 = __floats2half2_rn(v.x, v.y);
    __half2 p1 = __floats2half2_rn(v.z, v.w);
    uint2 u;
    u.x = *(uint32_t*)&p0; u.y = *(uint32_t*)&p1;
    dst[i] = u;
}

// ---------------------------------------------------------------------------
// fp16 NT GEMM via mma.sync: C[M,N] = A[M,K] @ B[N,K]^T + bias[N], fp32 out.
// CTA tile 128x256, K-slab 128. SMEM stage (96KB):
//   [0,16K) A kh0 | [16K,32K) A kh1 | [32K,64K) B kh0 | [64K,96K) B kh1
// 2-stage cp.async pipeline, 512 threads (16 warps 4x4, 32x64 per warp).
// Fragment software pipeline: A double-buffered across kk; B is a rolling
// buffer — b[p] is reloaded for kk+1 right after its 4 consuming HMMAs, so
// LDSM traffic interleaves with tensor work instead of bursting.
// ---------------------------------------------------------------------------
#define STG_BYTES 98304   // 32KB A + 64KB B
#define GSMEM (2 * STG_BYTES + 1024)
#define NTHREADS 512

__global__ __launch_bounds__(NTHREADS, 1)
void gemm_mma(const __half* __restrict__ A, const __half* __restrict__ B,
              const float* __restrict__ bias, float* __restrict__ C, int N)
{
    extern __shared__ char smem_raw[];
    const uint32_t sb = (smem_u32(smem_raw) + 1023) & ~1023u;
    const int tid  = threadIdx.x;
    const int lane = tid & 31;
    const int wid  = tid >> 5;
    const int wm   = wid >> 2;          // 0..3  (M, 32 rows)
    const int wn   = wid & 3;           // 0..3  (N, 64 cols)
    const int brow = blockIdx.y * 128;
    const int bcol = blockIdx.x * 256;

    float acc[2][8][4];
#pragma unroll
    for (int i = 0; i < 2; i++)
#pragma unroll
        for (int j = 0; j < 8; j++)
#pragma unroll
            for (int k = 0; k < 4; k++) acc[i][j][k] = 0.f;

    const int  lrow   = lane & 15;
    const int  lkb    = (lane >> 4) * 16;
    const uint32_t a_base = SWZ((wm * 32 + lrow) * 128 + lkb);
    const uint32_t b_base = SWZ((wn * 64 + lrow) * 128 + lkb);

    // ---- minimal-state cp.async addressing ----
    const int r0 = tid >> 3;
    const int c8 = (tid & 7) * 8;
    const __half* aptr = A + (size_t)(brow + r0) * Edim + c8;
    const __half* bptr = B + (size_t)(bcol + r0) * Edim + c8;
    const uint32_t saw = SWZ(r0 * 128 + (tid & 7) * 16);
    const uint32_t sa0 = sb + saw;
    const uint32_t sb0 = sb + 32768 + saw;

    auto load_stage = [&](uint32_t bo) {
        cp16(sa0 + bo,                 aptr);
        cp16(sa0 + bo + 8192,          aptr + 64 * Edim);
        cp16(sa0 + bo + 16384,         aptr + 64);
        cp16(sa0 + bo + 16384 + 8192,  aptr + 64 * Edim + 64);
#pragma unroll
        for (int j = 0; j < 4; j++) {
            cp16(sb0 + bo + j * 8192,          bptr + j * 64 * Edim);
            cp16(sb0 + bo + 32768 + j * 8192,  bptr + j * 64 * Edim + 64);
        }
        asm volatile("cp.async.commit_group;");
        aptr += 128;
        bptr += 128;
    };

    load_stage(0);

    // fragment addresses for a given kk (compile-time after unroll)
    auto a_addr = [&](uint32_t stg, int kk, int mt) {
        return stg + (uint32_t)(kk >> 2) * 16384 + ((a_base + mt * 2048) ^ ((uint32_t)(kk & 3) * 32));
    };
    auto b_addr = [&](uint32_t stg, int kk, int p) {
        return stg + 32768 + (uint32_t)(kk >> 2) * 32768 + ((b_base + p * 2048) ^ ((uint32_t)(kk & 3) * 32));
    };

    uint32_t a[2][2][4];   // [kk-buf][mt][frag]
    uint32_t b[4][4];      // rolling [p][frag]

    for (int s = 0; s < 8; ++s) {
        asm volatile("cp.async.wait_group 0;");
        __syncthreads();
        if (s < 7) load_stage((uint32_t)((s + 1) & 1) * STG_BYTES);

        const uint32_t stg = sb + (uint32_t)(s & 1) * STG_BYTES;

        // prologue for this slab: fragments for kk=0
#pragma unroll
        for (int mt = 0; mt < 2; mt++) ldm4(a[0][mt], a_addr(stg, 0, mt));
#pragma unroll
        for (int p = 0; p < 4; p++)    ldm4(b[p],    b_addr(stg, 0, p));

#pragma unroll
        for (int kk = 0; kk < 8; kk++) {
            const int cur = kk & 1;
            // prefetch A for kk+1 (independent of current HMMAs)
            if (kk < 7) {
#pragma unroll
                for (int mt = 0; mt < 2; mt++)
                    ldm4(a[cur ^ 1][mt], a_addr(stg, kk + 1, mt));
            }
            // consume b[p] with 4 HMMAs, then immediately reload it for kk+1
#pragma unroll
            for (int p = 0; p < 4; p++) {
#pragma unroll
                for (int q = 0; q < 2; q++) {
                    const int nt = 2 * p + q;
#pragma unroll
                    for (int mt = 0; mt < 2; mt++)
                        mma_f16(acc[mt][nt], a[cur][mt], b[p][q], b[p][q + 2]);
                }
                if (kk < 7) ldm4(b[p], b_addr(stg, kk + 1, p));
            }
        }
    }

    // ---- epilogue: bias add, float2 stores ----
    const int g  = lane >> 2;
    const int q2 = (lane & 3) * 2;
#pragma unroll
    for (int mt = 0; mt < 2; mt++) {
#pragma unroll
        for (int h = 0; h < 2; h++) {
            const int row = brow + wm * 32 + mt * 16 + g + h * 8;
#pragma unroll
            for (int nt = 0; nt < 8; nt++) {
                const int col = bcol + wn * 64 + nt * 8 + q2;
                float2 v;
                v.x = acc[mt][nt][2 * h + 0] + __ldg(bias + col + 0);
                v.y = acc[mt][nt][2 * h + 1] + __ldg(bias + col + 1);
                *(float2*)(C + (size_t)row * N + col) = v;
            }
        }
    }
}

// ---------------------------------------------------------------------------
// Per-position "head attention" (einsum-label bug replicated exactly).
// Emits fp16 output directly (feeds GEMM2's A operand).
// ---------------------------------------------------------------------------
__global__ __launch_bounds__(256)
void attn_kernel(const float* __restrict__ qkv, __half* __restrict__ oh)
{
    __shared__ __align__(16) float s[3 * Edim];
    __shared__ float en[Hh][Hh + 1];
    __shared__ float rinv[Hh];

    const int bp  = blockIdx.x;
    const int b   = bp >> 11;
    const int pos = bp & 2047;
    const int tid = threadIdx.x;

    {
        const float4* r4 = (const float4*)(qkv + (size_t)bp * 3072);
        float4* s4 = (float4*)s;
#pragma unroll
        for (int t = 0; t < 3; t++) s4[tid + t * 256] = r4[tid + t * 256];
    }
    __syncthreads();

    {
        const int i = tid >> 4;
        const int j = tid & 15;
        const float* q  = s + i * 64;
        const float* kp = s + 1024 + j * 64;
        float e = 0.f;
#pragma unroll
        for (int dd = 0; dd < 16; dd++) {
            const int d4 = ((dd + tid) & 15) * 4;
            float4 qv = *(const float4*)(q + d4);
            float4 kv = *(const float4*)(kp + d4);
            e += qv.x * kv.x + qv.y * kv.y + qv.z * kv.z + qv.w * kv.w;
        }
        en[i][j] = e * 0.03125f;   // 1/sqrt(1024)
    }
    __syncthreads();

    if (tid < Hh) {
        float m = -1e30f;
#pragma unroll
        for (int j = 0; j < Hh; j++) m = fmaxf(m, en[tid][j]);
        float sum = 0.f;
#pragma unroll
        for (int j = 0; j < Hh; j++) {
            const float v = __expf(en[tid][j] - m);
            en[tid][j] = v;
            sum += v;
        }
        rinv[tid] = 1.f / sum;
    }
    __syncthreads();

#pragma unroll
    for (int t0 = 0; t0 < 4; t0++) {
        const int t = tid + t0 * 256;
        const int i = t >> 6;
        const int d = t & 63;
        float o = 0.f;
#pragma unroll
        for (int l = 0; l < Hh; l++)
            o += en[i][l] * s[2048 + l * 64 + d];
        o *= rinv[i];
        const size_t idx = ((size_t)(b * Hh + i) * Nseq + pos) * Dd + d;
        oh[idx] = __float2half_rn(o);
    }
}

// ---------------------------------------------------------------------------
// launch
// ---------------------------------------------------------------------------
extern "C" void kernel_launch(void* const* d_in, const int* in_sizes, int n_in,
                              void* d_out, int out_size)
{
    const float* x    = (const float*)d_in[0];   // [16384,1024]
    const float* Wqkv = (const float*)d_in[1];   // [3072,1024]
    const float* bqkv = (const float*)d_in[2];
    const float* Wo   = (const float*)d_in[3];   // [1024,1024]
    const float* bo   = (const float*)d_in[4];
    float* out = (float*)d_out;

    float* qkv_buf;
    __half *xh, *ath, *wqh, *woh;
    cudaGetSymbolAddress((void**)&qkv_buf, g_qkv);
    cudaGetSymbolAddress((void**)&xh,  g_xh);
    cudaGetSymbolAddress((void**)&ath, g_ath);
    cudaGetSymbolAddress((void**)&wqh, g_wqh);
    cudaGetSymbolAddress((void**)&woh, g_woh);

    cudaFuncSetAttribute(gemm_mma, cudaFuncAttributeMaxDynamicSharedMemorySize, GSMEM);

    // 0) x, Wqkv, Wo -> fp16
    {
        int n4 = Mrows * Edim / 4;
        tohalf_kernel<<<(n4 + 255) / 256, 256>>>((const float4*)x, (uint2*)xh, n4);
        n4 = 3 * Edim * Edim / 4;
        tohalf_kernel<<<(n4 + 255) / 256, 256>>>((const float4*)Wqkv, (uint2*)wqh, n4);
        n4 = Edim * Edim / 4;
        tohalf_kernel<<<(n4 + 255) / 256, 256>>>((const float4*)Wo, (uint2*)woh, n4);
    }

    // 1) qkv = x @ Wqkv^T + bqkv   [16384, 3072]
    {
        dim3 grid(3 * Edim / 256, Mrows / 128);
        gemm_mma<<<grid, NTHREADS, GSMEM>>>(xh, wqh, bqkv, qkv_buf, 3 * Edim);
    }

    // 2) per-position head-attention -> fp16 in raw [B,H,N,D] layout
    attn_kernel<<<Mrows, 256>>>(qkv_buf, ath);

    // 3) out = Y @ Wo^T + bo   [16384, 1024]
    {
        dim3 grid(Edim / 256, Mrows / 128);
        gemm_mma<<<grid, NTHREADS, GSMEM>>>(ath, woh, bo, out, Edim);
    }
}

// round 13
// speedup vs baseline: 1.0677x; 1.0677x over previous
#include <cuda_runtime.h>
#include <cuda_fp16.h>
#include <cstdint>

// Problem constants
#define Bdim 8
#define Nseq 2048
#define Edim 1024
#define Hh   16
#define Dd   64
#define Mrows (Bdim * Nseq)      // 16384

// ---------------------------------------------------------------------------
// Scratch (allocation-free rule: __device__ globals)
// ---------------------------------------------------------------------------
__device__ __half  g_qkvh[(size_t)Mrows * 3 * Edim];  // 96 MB fp16 qkv
__device__ __half  g_xh [(size_t)Mrows * Edim];       // x as fp16
__device__ __half  g_ath[(size_t)Mrows * Edim];       // attn out as fp16
__device__ __half  g_wqh[(size_t)3 * Edim * Edim];    // Wqkv fp16
__device__ __half  g_woh[(size_t)Edim * Edim];        // Wo fp16

// ---------------------------------------------------------------------------
// Helpers (baseline-feature PTX only: cp.async, ldmatrix, mma.sync — sm_80+)
// ---------------------------------------------------------------------------
__device__ __forceinline__ uint32_t smem_u32(const void* p) {
    uint32_t a;
    asm("{ .reg .u64 t; cvta.to.shared.u64 t, %1; cvt.u32.u64 %0, t; }" : "=r"(a) : "l"(p));
    return a;
}
#define SWZ(x) ((x) ^ (((x) >> 3) & 0x70))

__device__ __forceinline__ void cp16(uint32_t dst, const void* src) {
    asm volatile("cp.async.cg.shared.global [%0], [%1], 16;" :: "r"(dst), "l"(src));
}
__device__ __forceinline__ void ldm4(uint32_t* r, uint32_t addr) {
    asm volatile("ldmatrix.sync.aligned.m8n8.x4.shared.b16 {%0,%1,%2,%3}, [%4];"
                 : "=r"(r[0]), "=r"(r[1]), "=r"(r[2]), "=r"(r[3]) : "r"(addr));
}
__device__ __forceinline__ void mma_f16(float* c, const uint32_t* a, uint32_t b0, uint32_t b1) {
    asm volatile(
        "mma.sync.aligned.m16n8k16.row.col.f32.f16.f16.f32 "
        "{%0,%1,%2,%3}, {%4,%5,%6,%7}, {%8,%9}, {%0,%1,%2,%3};"
        : "+f"(c[0]), "+f"(c[1]), "+f"(c[2]), "+f"(c[3])
        : "r"(a[0]), "r"(a[1]), "r"(a[2]), "r"(a[3]), "r"(b0), "r"(b1));
}

// ---------------------------------------------------------------------------
// fp32 -> fp16 conversion kernel
// ---------------------------------------------------------------------------
__global__ __launch_bounds__(256)
void tohalf_kernel(const float4* __restrict__ src, uint2* __restrict__ dst, int n4)
{
    int i = blockIdx.x * 256 + threadIdx.x;
    if (i >= n4) return;
    float4 v = src[i];
    __half2 p0 = __floats2half2_rn(v.x, v.y);
    __half2 p1 = __floats2half2_rn(v.z, v.w);
    uint2 u;
    u.x = *(uint32_t*)&p0; u.y = *(uint32_t*)&p1;
    dst[i] = u;
}

// ---------------------------------------------------------------------------
// fp16 NT GEMM via mma.sync: C[M,N] = A[M,K] @ B[N,K]^T + bias[N].
// Output fp32 or fp16 (template). CTA tile 128x256, K-slab 128.
// SMEM stage (96KB): A kh0|A kh1|B kh0|B kh1, 128B rows, SW128-swizzled.
// 2-stage pipeline; the 12 cp.async chunks per thread for the NEXT stage are
// spread across kk=0..5 (2/kk, commit at kk=5) so the LSU issue burst
// interleaves with tensor work instead of stalling the slab start.
// ---------------------------------------------------------------------------
#define STG_BYTES 98304   // 32KB A + 64KB B
#define GSMEM (2 * STG_BYTES + 1024)
#define NTHREADS 512

template<bool HALF_OUT>
__global__ __launch_bounds__(NTHREADS, 1)
void gemm_mma(const __half* __restrict__ A, const __half* __restrict__ B,
              const float* __restrict__ bias, void* __restrict__ Cv, int N)
{
    extern __shared__ char smem_raw[];
    const uint32_t sb = (smem_u32(smem_raw) + 1023) & ~1023u;
    const int tid  = threadIdx.x;
    const int lane = tid & 31;
    const int wid  = tid >> 5;
    const int wm   = wid >> 2;          // 0..3  (M, 32 rows)
    const int wn   = wid & 3;           // 0..3  (N, 64 cols)
    const int brow = blockIdx.y * 128;
    const int bcol = blockIdx.x * 256;

    float acc[2][8][4];
#pragma unroll
    for (int i = 0; i < 2; i++)
#pragma unroll
        for (int j = 0; j < 8; j++)
#pragma unroll
            for (int k = 0; k < 4; k++) acc[i][j][k] = 0.f;

    const int  lrow   = lane & 15;
    const int  lkb    = (lane >> 4) * 16;
    const uint32_t a_base = SWZ((wm * 32 + lrow) * 128 + lkb);
    const uint32_t b_base = SWZ((wn * 64 + lrow) * 128 + lkb);

    // ---- minimal-state cp.async addressing ----
    const int r0 = tid >> 3;
    const int c8 = (tid & 7) * 8;
    const __half* aptr = A + (size_t)(brow + r0) * Edim + c8;
    const __half* bptr = B + (size_t)(bcol + r0) * Edim + c8;
    const uint32_t saw = SWZ(r0 * 128 + (tid & 7) * 16);
    const uint32_t sa0 = sb + saw;
    const uint32_t sb0 = sb + 32768 + saw;

    // chunk tables (fold to immediates under full unroll)
    const uint32_t ASO[4] = {0u, 8192u, 16384u, 24576u};
    const size_t   AGO[4] = {0, (size_t)64 * Edim, 64, (size_t)64 * Edim + 64};
    const uint32_t BSO[8] = {0u, 8192u, 16384u, 24576u, 32768u, 40960u, 49152u, 57344u};
    const size_t   BGO[8] = {0, (size_t)64 * Edim, (size_t)128 * Edim, (size_t)192 * Edim,
                             64, (size_t)64 * Edim + 64, (size_t)128 * Edim + 64, (size_t)192 * Edim + 64};

    // full-stage burst load (prologue only)
    auto load_stage = [&](uint32_t bo) {
#pragma unroll
        for (int i = 0; i < 4; i++)  cp16(sa0 + bo + ASO[i], aptr + AGO[i]);
#pragma unroll
        for (int i = 0; i < 8; i++)  cp16(sb0 + bo + BSO[i], bptr + BGO[i]);
        asm volatile("cp.async.commit_group;");
        aptr += 128;
        bptr += 128;
    };

    load_stage(0);

    auto a_addr = [&](uint32_t stg, int kk, int mt) {
        return stg + (uint32_t)(kk >> 2) * 16384 + ((a_base + mt * 2048) ^ ((uint32_t)(kk & 3) * 32));
    };
    auto b_addr = [&](uint32_t stg, int kk, int p) {
        return stg + 32768 + (uint32_t)(kk >> 2) * 32768 + ((b_base + p * 2048) ^ ((uint32_t)(kk & 3) * 32));
    };

    uint32_t a[2][2][4];   // [kk-buf][mt][frag]
    uint32_t b[4][4];      // rolling [p][frag]

    for (int s = 0; s < 8; ++s) {
        asm volatile("cp.async.wait_group 0;");
        __syncthreads();

        const uint32_t stg = sb + (uint32_t)(s & 1) * STG_BYTES;
        const uint32_t nbo = (uint32_t)((s + 1) & 1) * STG_BYTES;
        const bool more = (s < 7);

        // fragments for kk=0
#pragma unroll
        for (int mt = 0; mt < 2; mt++) ldm4(a[0][mt], a_addr(stg, 0, mt));
#pragma unroll
        for (int p = 0; p < 4; p++)    ldm4(b[p],    b_addr(stg, 0, p));

#pragma unroll
        for (int kk = 0; kk < 8; kk++) {
            // spread next-stage cp.async: 2 chunks per kk for kk=0..5
            if (more && kk < 6) {
#pragma unroll
                for (int t = 0; t < 2; t++) {
                    const int i = kk * 2 + t;
                    if (i < 4) cp16(sa0 + nbo + ASO[i], aptr + AGO[i]);
                    else       cp16(sb0 + nbo + BSO[i - 4], bptr + BGO[i - 4]);
                }
                if (kk == 5) asm volatile("cp.async.commit_group;");
            }
            const int cur = kk & 1;
            if (kk < 7) {
#pragma unroll
                for (int mt = 0; mt < 2; mt++)
                    ldm4(a[cur ^ 1][mt], a_addr(stg, kk + 1, mt));
            }
#pragma unroll
            for (int p = 0; p < 4; p++) {
#pragma unroll
                for (int q = 0; q < 2; q++) {
                    const int nt = 2 * p + q;
#pragma unroll
                    for (int mt = 0; mt < 2; mt++)
                        mma_f16(acc[mt][nt], a[cur][mt], b[p][q], b[p][q + 2]);
                }
                if (kk < 7) ldm4(b[p], b_addr(stg, kk + 1, p));
            }
        }
        if (more) { aptr += 128; bptr += 128; }
    }

    // ---- epilogue: bias add ----
    const int g  = lane >> 2;
    const int q2 = (lane & 3) * 2;
#pragma unroll
    for (int mt = 0; mt < 2; mt++) {
#pragma unroll
        for (int h = 0; h < 2; h++) {
            const int row = brow + wm * 32 + mt * 16 + g + h * 8;
#pragma unroll
            for (int nt = 0; nt < 8; nt++) {
                const int col = bcol + wn * 64 + nt * 8 + q2;
                const float vx = acc[mt][nt][2 * h + 0] + __ldg(bias + col + 0);
                const float vy = acc[mt][nt][2 * h + 1] + __ldg(bias + col + 1);
                if (HALF_OUT) {
                    __half2 hv = __floats2half2_rn(vx, vy);
                    *(uint32_t*)((__half*)Cv + (size_t)row * N + col) = *(uint32_t*)&hv;
                } else {
                    float2 v2 = make_float2(vx, vy);
                    *(float2*)((float*)Cv + (size_t)row * N + col) = v2;
                }
            }
        }
    }
}

// ---------------------------------------------------------------------------
// Per-position "head attention" (einsum-label bug replicated exactly).
// Reads fp16 qkv, computes in fp32, emits fp16 output.
// ---------------------------------------------------------------------------
__global__ __launch_bounds__(256)
void attn_kernel(const __half* __restrict__ qkv, __half* __restrict__ oh)
{
    __shared__ __align__(16) float s[3 * Edim];
    __shared__ float en[Hh][Hh + 1];
    __shared__ float rinv[Hh];

    const int bp  = blockIdx.x;
    const int b   = bp >> 11;
    const int pos = bp & 2047;
    const int tid = threadIdx.x;

    {
        const uint2* r2 = (const uint2*)(qkv + (size_t)bp * 3072);   // 4 halfs each
        float4* s4 = (float4*)s;
#pragma unroll
        for (int t = 0; t < 3; t++) {
            const int idx = tid + t * 256;     // 768 uint2 total
            uint2 u = r2[idx];
            __half2 h0 = *(__half2*)&u.x;
            __half2 h1 = *(__half2*)&u.y;
            float2 f0 = __half22float2(h0);
            float2 f1 = __half22float2(h1);
            s4[idx] = make_float4(f0.x, f0.y, f1.x, f1.y);
        }
    }
    __syncthreads();

    {
        const int i = tid >> 4;
        const int j = tid & 15;
        const float* q  = s + i * 64;
        const float* kp = s + 1024 + j * 64;
        float e = 0.f;
#pragma unroll
        for (int dd = 0; dd < 16; dd++) {
            const int d4 = ((dd + tid) & 15) * 4;
            float4 qv = *(const float4*)(q + d4);
            float4 kv = *(const float4*)(kp + d4);
            e += qv.x * kv.x + qv.y * kv.y + qv.z * kv.z + qv.w * kv.w;
        }
        en[i][j] = e * 0.03125f;   // 1/sqrt(1024)
    }
    __syncthreads();

    if (tid < Hh) {
        float m = -1e30f;
#pragma unroll
        for (int j = 0; j < Hh; j++) m = fmaxf(m, en[tid][j]);
        float sum = 0.f;
#pragma unroll
        for (int j = 0; j < Hh; j++) {
            const float v = __expf(en[tid][j] - m);
            en[tid][j] = v;
            sum += v;
        }
        rinv[tid] = 1.f / sum;
    }
    __syncthreads();

#pragma unroll
    for (int t0 = 0; t0 < 4; t0++) {
        const int t = tid + t0 * 256;
        const int i = t >> 6;
        const int d = t & 63;
        float o = 0.f;
#pragma unroll
        for (int l = 0; l < Hh; l++)
            o += en[i][l] * s[2048 + l * 64 + d];
        o *= rinv[i];
        const size_t idx = ((size_t)(b * Hh + i) * Nseq + pos) * Dd + d;
        oh[idx] = __float2half_rn(o);
    }
}

// ---------------------------------------------------------------------------
// launch
// ---------------------------------------------------------------------------
extern "C" void kernel_launch(void* const* d_in, const int* in_sizes, int n_in,
                              void* d_out, int out_size)
{
    const float* x    = (const float*)d_in[0];   // [16384,1024]
    const float* Wqkv = (const float*)d_in[1];   // [3072,1024]
    const float* bqkv = (const float*)d_in[2];
    const float* Wo   = (const float*)d_in[3];   // [1024,1024]
    const float* bo   = (const float*)d_in[4];
    float* out = (float*)d_out;

    __half *qkvh, *xh, *ath, *wqh, *woh;
    cudaGetSymbolAddress((void**)&qkvh, g_qkvh);
    cudaGetSymbolAddress((void**)&xh,  g_xh);
    cudaGetSymbolAddress((void**)&ath, g_ath);
    cudaGetSymbolAddress((void**)&wqh, g_wqh);
    cudaGetSymbolAddress((void**)&woh, g_woh);

    cudaFuncSetAttribute(gemm_mma<true>,  cudaFuncAttributeMaxDynamicSharedMemorySize, GSMEM);
    cudaFuncSetAttribute(gemm_mma<false>, cudaFuncAttributeMaxDynamicSharedMemorySize, GSMEM);

    // 0) x, Wqkv, Wo -> fp16
    {
        int n4 = Mrows * Edim / 4;
        tohalf_kernel<<<(n4 + 255) / 256, 256>>>((const float4*)x, (uint2*)xh, n4);
        n4 = 3 * Edim * Edim / 4;
        tohalf_kernel<<<(n4 + 255) / 256, 256>>>((const float4*)Wqkv, (uint2*)wqh, n4);
        n4 = Edim * Edim / 4;
        tohalf_kernel<<<(n4 + 255) / 256, 256>>>((const float4*)Wo, (uint2*)woh, n4);
    }

    // 1) qkv = x @ Wqkv^T + bqkv   [16384, 3072]  (fp16 out)
    {
        dim3 grid(3 * Edim / 256, Mrows / 128);
        gemm_mma<true><<<grid, NTHREADS, GSMEM>>>(xh, wqh, bqkv, qkvh, 3 * Edim);
    }

    // 2) per-position head-attention -> fp16 in raw [B,H,N,D] layout
    attn_kernel<<<Mrows, 256>>>(qkvh, ath);

    // 3) out = Y @ Wo^T + bo   [16384, 1024]  (fp32 out)
    {
        dim3 grid(Edim / 256, Mrows / 128);
        gemm_mma<false><<<grid, NTHREADS, GSMEM>>>(ath, woh, bo, out, Edim);
    }
}

// round 14
// speedup vs baseline: 1.1249x; 1.0536x over previous
#include <cuda_runtime.h>
#include <cuda_fp16.h>
#include <cstdint>

// Problem constants
#define Bdim 8
#define Nseq 2048
#define Edim 1024
#define Hh   16
#define Dd   64
#define Mrows (Bdim * Nseq)      // 16384

// ---------------------------------------------------------------------------
// Scratch (allocation-free rule: __device__ globals)
// ---------------------------------------------------------------------------
__device__ __half  g_qkvh[(size_t)Mrows * 3 * Edim];  // 96 MB fp16 qkv
__device__ __half  g_xh [(size_t)Mrows * Edim];       // x as fp16
__device__ __half  g_ath[(size_t)Mrows * Edim];       // attn out as fp16
__device__ __half  g_wqh[(size_t)3 * Edim * Edim];    // Wqkv fp16
__device__ __half  g_woh[(size_t)Edim * Edim];        // Wo fp16

// ---------------------------------------------------------------------------
// Helpers (baseline-feature PTX only: cp.async, ldmatrix, mma.sync — sm_80+)
// ---------------------------------------------------------------------------
__device__ __forceinline__ uint32_t smem_u32(const void* p) {
    uint32_t a;
    asm("{ .reg .u64 t; cvta.to.shared.u64 t, %1; cvt.u32.u64 %0, t; }" : "=r"(a) : "l"(p));
    return a;
}
#define SWZ(x) ((x) ^ (((x) >> 3) & 0x70))

__device__ __forceinline__ void cp16(uint32_t dst, const void* src) {
    asm volatile("cp.async.cg.shared.global [%0], [%1], 16;" :: "r"(dst), "l"(src));
}
__device__ __forceinline__ void ldm4(uint32_t* r, uint32_t addr) {
    asm volatile("ldmatrix.sync.aligned.m8n8.x4.shared.b16 {%0,%1,%2,%3}, [%4];"
                 : "=r"(r[0]), "=r"(r[1]), "=r"(r[2]), "=r"(r[3]) : "r"(addr));
}
__device__ __forceinline__ void mma_f16(float* c, const uint32_t* a, uint32_t b0, uint32_t b1) {
    asm volatile(
        "mma.sync.aligned.m16n8k16.row.col.f32.f16.f16.f32 "
        "{%0,%1,%2,%3}, {%4,%5,%6,%7}, {%8,%9}, {%0,%1,%2,%3};"
        : "+f"(c[0]), "+f"(c[1]), "+f"(c[2]), "+f"(c[3])
        : "r"(a[0]), "r"(a[1]), "r"(a[2]), "r"(a[3]), "r"(b0), "r"(b1));
}

// ---------------------------------------------------------------------------
// fp32 -> fp16 conversion kernel
// ---------------------------------------------------------------------------
__global__ __launch_bounds__(256)
void tohalf_kernel(const float4* __restrict__ src, uint2* __restrict__ dst, int n4)
{
    int i = blockIdx.x * 256 + threadIdx.x;
    if (i >= n4) return;
    float4 v = src[i];
    __half2 p0 = __floats2half2_rn(v.x, v.y);
    __half2 p1 = __floats2half2_rn(v.z, v.w);
    uint2 u;
    u.x = *(uint32_t*)&p0; u.y = *(uint32_t*)&p1;
    dst[i] = u;
}

// ---------------------------------------------------------------------------
// fp16 NT GEMM via mma.sync: C[M,N] = A[M,K] @ B[N,K]^T + bias[N].
// CTA tile 128x128, 256 threads (8 warps 4x2, 32x64 per warp), K-slab 64.
// 3-stage cp.async ring (32KB/stage: A 16KB | B 16KB, 128B rows, SW128),
// 2 CTAs/SM (launch_bounds(256,2)) so the two CTAs' load/compute phases
// interleave across slab barriers (sum -> max of tensor & smem time).
// Stage for slab s+2 is issued during slab s -> a full slab of latency slack.
// ---------------------------------------------------------------------------
#define STG_BYTES 32768
#define GSMEM (3 * STG_BYTES + 1024)
#define NTHREADS 256

template<bool HALF_OUT>
__global__ __launch_bounds__(NTHREADS, 2)
void gemm_mma(const __half* __restrict__ A, const __half* __restrict__ B,
              const float* __restrict__ bias, void* __restrict__ Cv, int N)
{
    extern __shared__ char smem_raw[];
    const uint32_t sb = (smem_u32(smem_raw) + 1023) & ~1023u;
    const int tid  = threadIdx.x;
    const int lane = tid & 31;
    const int wid  = tid >> 5;
    const int wm   = wid >> 1;          // 0..3  (M, 32 rows)
    const int wn   = wid & 1;           // 0..1  (N, 64 cols)
    const int brow = blockIdx.y * 128;
    const int bcol = blockIdx.x * 128;

    float acc[2][8][4];
#pragma unroll
    for (int i = 0; i < 2; i++)
#pragma unroll
        for (int j = 0; j < 8; j++)
#pragma unroll
            for (int k = 0; k < 4; k++) acc[i][j][k] = 0.f;

    const int  lrow   = lane & 15;
    const int  lkb    = (lane >> 4) * 16;
    const uint32_t a_base = SWZ((wm * 32 + lrow) * 128 + lkb);
    const uint32_t b_base = SWZ((wn * 64 + lrow) * 128 + lkb);

    // ---- cp.async addressing: 8 chunks/thread/slab (4 A + 4 B) ----
    const int r0 = tid >> 3;            // 0..31
    const int c8 = (tid & 7) * 8;
    const __half* aptr = A + (size_t)(brow + r0) * Edim + c8;
    const __half* bptr = B + (size_t)(bcol + r0) * Edim + c8;
    const uint32_t saw = SWZ(r0 * 128 + (tid & 7) * 16);
    const uint32_t sa0 = sb + saw;
    const uint32_t sb0 = sb + 16384 + saw;

    // full-stage load (prologue)
    auto load_stage = [&](uint32_t bo) {
#pragma unroll
        for (int j = 0; j < 4; j++) {
            cp16(sa0 + bo + j * 4096, aptr + (size_t)j * 32 * Edim);
            cp16(sb0 + bo + j * 4096, bptr + (size_t)j * 32 * Edim);
        }
        asm volatile("cp.async.commit_group;");
        aptr += 64;
        bptr += 64;
    };

    load_stage(0);
    load_stage(STG_BYTES);

    auto a_addr = [&](uint32_t stg, int kk, int mt) {
        return stg + ((a_base + mt * 2048) ^ ((uint32_t)kk * 32));
    };
    auto b_addr = [&](uint32_t stg, int kk, int p) {
        return stg + 16384 + ((b_base + p * 2048) ^ ((uint32_t)kk * 32));
    };

    uint32_t a[2][2][4];   // [kk-buf][mt][frag]
    uint32_t b[4][4];      // rolling [p][frag]

    for (int s = 0; s < 16; ++s) {
        if (s < 15) asm volatile("cp.async.wait_group 1;");
        else        asm volatile("cp.async.wait_group 0;");
        __syncthreads();

        const uint32_t stg = sb + (uint32_t)(s % 3) * STG_BYTES;
        const uint32_t nbo = (uint32_t)((s + 2) % 3) * STG_BYTES;
        const bool more = (s < 14);

        // fragments for kk=0
#pragma unroll
        for (int mt = 0; mt < 2; mt++) ldm4(a[0][mt], a_addr(stg, 0, mt));
#pragma unroll
        for (int p = 0; p < 4; p++)    ldm4(b[p],    b_addr(stg, 0, p));

#pragma unroll
        for (int kk = 0; kk < 4; kk++) {
            // spread next-next-stage cp.async: 2 chunks per kk
            if (more) {
#pragma unroll
                for (int t = 0; t < 2; t++) {
                    const int i = kk * 2 + t;
                    if (i < 4) cp16(sa0 + nbo + i * 4096, aptr + (size_t)i * 32 * Edim);
                    else       cp16(sb0 + nbo + (i - 4) * 4096, bptr + (size_t)(i - 4) * 32 * Edim);
                }
            }
            const int cur = kk & 1;
            if (kk < 3) {
#pragma unroll
                for (int mt = 0; mt < 2; mt++)
                    ldm4(a[cur ^ 1][mt], a_addr(stg, kk + 1, mt));
            }
#pragma unroll
            for (int p = 0; p < 4; p++) {
#pragma unroll
                for (int q = 0; q < 2; q++) {
                    const int nt = 2 * p + q;
#pragma unroll
                    for (int mt = 0; mt < 2; mt++)
                        mma_f16(acc[mt][nt], a[cur][mt], b[p][q], b[p][q + 2]);
                }
                if (kk < 3) ldm4(b[p], b_addr(stg, kk + 1, p));
            }
        }
        if (more) {
            asm volatile("cp.async.commit_group;");
            aptr += 64;
            bptr += 64;
        }
    }

    // ---- epilogue: bias add ----
    const int g  = lane >> 2;
    const int q2 = (lane & 3) * 2;
#pragma unroll
    for (int mt = 0; mt < 2; mt++) {
#pragma unroll
        for (int h = 0; h < 2; h++) {
            const int row = brow + wm * 32 + mt * 16 + g + h * 8;
#pragma unroll
            for (int nt = 0; nt < 8; nt++) {
                const int col = bcol + wn * 64 + nt * 8 + q2;
                const float vx = acc[mt][nt][2 * h + 0] + __ldg(bias + col + 0);
                const float vy = acc[mt][nt][2 * h + 1] + __ldg(bias + col + 1);
                if (HALF_OUT) {
                    __half2 hv = __floats2half2_rn(vx, vy);
                    *(uint32_t*)((__half*)Cv + (size_t)row * N + col) = *(uint32_t*)&hv;
                } else {
                    float2 v2 = make_float2(vx, vy);
                    *(float2*)((float*)Cv + (size_t)row * N + col) = v2;
                }
            }
        }
    }
}

// ---------------------------------------------------------------------------
// Per-position "head attention" (einsum-label bug replicated exactly).
// Reads fp16 qkv, computes in fp32, emits fp16 output.
// ---------------------------------------------------------------------------
__global__ __launch_bounds__(256)
void attn_kernel(const __half* __restrict__ qkv, __half* __restrict__ oh)
{
    __shared__ __align__(16) float s[3 * Edim];
    __shared__ float en[Hh][Hh + 1];
    __shared__ float rinv[Hh];

    const int bp  = blockIdx.x;
    const int b   = bp >> 11;
    const int pos = bp & 2047;
    const int tid = threadIdx.x;

    {
        const uint2* r2 = (const uint2*)(qkv + (size_t)bp * 3072);
        float4* s4 = (float4*)s;
#pragma unroll
        for (int t = 0; t < 3; t++) {
            const int idx = tid + t * 256;
            uint2 u = r2[idx];
            __half2 h0 = *(__half2*)&u.x;
            __half2 h1 = *(__half2*)&u.y;
            float2 f0 = __half22float2(h0);
            float2 f1 = __half22float2(h1);
            s4[idx] = make_float4(f0.x, f0.y, f1.x, f1.y);
        }
    }
    __syncthreads();

    {
        const int i = tid >> 4;
        const int j = tid & 15;
        const float* q  = s + i * 64;
        const float* kp = s + 1024 + j * 64;
        float e = 0.f;
#pragma unroll
        for (int dd = 0; dd < 16; dd++) {
            const int d4 = ((dd + tid) & 15) * 4;
            float4 qv = *(const float4*)(q + d4);
            float4 kv = *(const float4*)(kp + d4);
            e += qv.x * kv.x + qv.y * kv.y + qv.z * kv.z + qv.w * kv.w;
        }
        en[i][j] = e * 0.03125f;   // 1/sqrt(1024)
    }
    __syncthreads();

    if (tid < Hh) {
        float m = -1e30f;
#pragma unroll
        for (int j = 0; j < Hh; j++) m = fmaxf(m, en[tid][j]);
        float sum = 0.f;
#pragma unroll
        for (int j = 0; j < Hh; j++) {
            const float v = __expf(en[tid][j] - m);
            en[tid][j] = v;
            sum += v;
        }
        rinv[tid] = 1.f / sum;
    }
    __syncthreads();

#pragma unroll
    for (int t0 = 0; t0 < 4; t0++) {
        const int t = tid + t0 * 256;
        const int i = t >> 6;
        const int d = t & 63;
        float o = 0.f;
#pragma unroll
        for (int l = 0; l < Hh; l++)
            o += en[i][l] * s[2048 + l * 64 + d];
        o *= rinv[i];
        const size_t idx = ((size_t)(b * Hh + i) * Nseq + pos) * Dd + d;
        oh[idx] = __float2half_rn(o);
    }
}

// ---------------------------------------------------------------------------
// launch
// ---------------------------------------------------------------------------
extern "C" void kernel_launch(void* const* d_in, const int* in_sizes, int n_in,
                              void* d_out, int out_size)
{
    const float* x    = (const float*)d_in[0];   // [16384,1024]
    const float* Wqkv = (const float*)d_in[1];   // [3072,1024]
    const float* bqkv = (const float*)d_in[2];
    const float* Wo   = (const float*)d_in[3];   // [1024,1024]
    const float* bo   = (const float*)d_in[4];
    float* out = (float*)d_out;

    __half *qkvh, *xh, *ath, *wqh, *woh;
    cudaGetSymbolAddress((void**)&qkvh, g_qkvh);
    cudaGetSymbolAddress((void**)&xh,  g_xh);
    cudaGetSymbolAddress((void**)&ath, g_ath);
    cudaGetSymbolAddress((void**)&wqh, g_wqh);
    cudaGetSymbolAddress((void**)&woh, g_woh);

    cudaFuncSetAttribute(gemm_mma<true>,  cudaFuncAttributeMaxDynamicSharedMemorySize, GSMEM);
    cudaFuncSetAttribute(gemm_mma<false>, cudaFuncAttributeMaxDynamicSharedMemorySize, GSMEM);

    // 0) x, Wqkv, Wo -> fp16
    {
        int n4 = Mrows * Edim / 4;
        tohalf_kernel<<<(n4 + 255) / 256, 256>>>((const float4*)x, (uint2*)xh, n4);
        n4 = 3 * Edim * Edim / 4;
        tohalf_kernel<<<(n4 + 255) / 256, 256>>>((const float4*)Wqkv, (uint2*)wqh, n4);
        n4 = Edim * Edim / 4;
        tohalf_kernel<<<(n4 + 255) / 256, 256>>>((const float4*)Wo, (uint2*)woh, n4);
    }

    // 1) qkv = x @ Wqkv^T + bqkv   [16384, 3072]  (fp16 out)
    {
        dim3 grid(3 * Edim / 128, Mrows / 128);
        gemm_mma<true><<<grid, NTHREADS, GSMEM>>>(xh, wqh, bqkv, qkvh, 3 * Edim);
    }

    // 2) per-position head-attention -> fp16 in raw [B,H,N,D] layout
    attn_kernel<<<Mrows, 256>>>(qkvh, ath);

    // 3) out = Y @ Wo^T + bo   [16384, 1024]  (fp32 out)
    {
        dim3 grid(Edim / 128, Mrows / 128);
        gemm_mma<false><<<grid, NTHREADS, GSMEM>>>(ath, woh, bo, out, Edim);
    }
}